// round 13
// baseline (speedup 1.0000x reference)
#include <cuda_runtime.h>
#include <cooperative_groups.h>
namespace cg = cooperative_groups;

#define EMB 100
#define BOT 5
#define NT  256
#define FULLMASK 0xffffffffu

// grid = 2*B, cluster (2,1,1): CTA pair {2b, 2b+1} cooperates on row b.
// Histogram bins split across the pair by word parity (25KB each); DSMEM
// atomics route increments to the owning CTA. Each CTA gathers its half of
// the tokens. 2 CTAs/SM co-resident -> independent barrier domains fill each
// other's latency bubbles.
__global__ void __launch_bounds__(NT, 2) __cluster_dims__(2, 1, 1)
doc_model_kernel(const int* __restrict__ x,
                 const float* __restrict__ we,
                 const float* __restrict__ idf,
                 const float* __restrict__ fc1w,
                 const float* __restrict__ fc1b,
                 const float* __restrict__ fc2w,
                 const float* __restrict__ fc2b,
                 float* __restrict__ out,
                 int S, int V)
{
    extern __shared__ unsigned int smem[];
    const int histW = (V + 3) >> 2;                      // u8-packed words (global)
    const int histL = ((((histW + 1) >> 1) + 3) & ~3);   // local half, 16B padded
    unsigned int* hist = smem;                 // histL words (this CTA's bins)
    float* stage = (float*)(hist + histL);     // 8 warps * 256 floats
    float* zp    = stage + 8 * 256;            // 8
    float* hw    = zp + 8;                     // 8*6 fc1 warp partials
    float* hself = hw + 48;                    // 8 (5 used)
    float* hpeer = hself + 8;                  // 8 (peer deposits 5)
    float* zpeer = hpeer + 8;                  // 4 (peer deposits 1)
    float* hv    = zpeer + 4;                  // 8

    cg::cluster_group cluster = cg::this_cluster();
    const unsigned rank = cluster.block_rank();

    const int tid  = threadIdx.x;
    const int warp = tid >> 5;
    const int lane = tid & 31;
    const int b    = blockIdx.x >> 1;
    const int half = S >> 1;                   // 1024 tokens per CTA

    // ---- own token block first (one LDG.128/thread; hides behind zeroing)
    const int* xr = x + (long long)b * S + (int)rank * half;
    const int4 t4 = *(const int4*)(xr + (warp << 7) + (lane << 2));

    // ---- zero own half-histogram (vectorized)
    uint4* h4 = (uint4*)hist;
    const uint4 z4 = make_uint4(0u, 0u, 0u, 0u);
    for (int i = tid; i < (histL >> 2); i += NT) h4[i] = z4;

    // idf gathers issue before the cluster barrier
    const float i0 = __ldg(&idf[t4.x]);
    const float i1 = __ldg(&idf[t4.y]);
    const float i2 = __ldg(&idf[t4.z]);
    const float i3 = __ldg(&idf[t4.w]);

    unsigned int* peerHist = cluster.map_shared_rank(hist, rank ^ 1);

    cluster.sync();   // S1: both half-histograms zeroed

    // ---- histogram increments routed by owner = (word & 1); fire-and-forget
    {
        const int w0 = t4.x >> 2, w1 = t4.y >> 2, w2 = t4.z >> 2, w3 = t4.w >> 2;
        unsigned int* p0 = (((unsigned)w0 & 1u) == rank ? hist : peerHist) + (w0 >> 1);
        unsigned int* p1 = (((unsigned)w1 & 1u) == rank ? hist : peerHist) + (w1 >> 1);
        unsigned int* p2 = (((unsigned)w2 & 1u) == rank ? hist : peerHist) + (w2 >> 1);
        unsigned int* p3 = (((unsigned)w3 & 1u) == rank ? hist : peerHist) + (w3 >> 1);
        atomicAdd(p0, 1u << ((t4.x & 3) << 3));
        atomicAdd(p1, 1u << ((t4.y & 3) << 3));
        atomicAdd(p2, 1u << ((t4.z & 3) << 3));
        atomicAdd(p3, 1u << ((t4.w & 3) << 3));
    }

    // ---- stage (byte-offset, idf) pairs for the count-free gather
    float4* stW = (float4*)(stage + (warp << 8));
    stW[(lane << 1)]     = make_float4(__int_as_float(t4.x * (EMB * 4)), i0,
                                       __int_as_float(t4.y * (EMB * 4)), i1);
    stW[(lane << 1) + 1] = make_float4(__int_as_float(t4.z * (EMB * 4)), i2,
                                       __int_as_float(t4.w * (EMB * 4)), i3);

    // half-Z (idf only)
    float z = (i0 + i1) + (i2 + i3);
    #pragma unroll
    for (int o = 16; o; o >>= 1) z += __shfl_xor_sync(FULLMASK, z, o);
    if (lane == 0) zp[warp] = z;
    __syncthreads();                 // zp + stage visible CTA-wide

    float z_own = 0.f;
    #pragma unroll
    for (int i = 0; i < 8; i++) z_own += zp[i];
    if (tid == 0) {
        float* pz = cluster.map_shared_rank(zpeer, rank ^ 1);
        pz[0] = z_own;               // ordered by S2's release
    }

    // ---- MAIN GATHER (overlaps both CTAs' atomics completing)
    const bool active = lane < (EMB / 4);
    const int  eoff   = lane << 4;
    const char* web = (const char*)we;
    float4 acc0 = make_float4(0.f, 0.f, 0.f, 0.f);
    float4 acc1 = make_float4(0.f, 0.f, 0.f, 0.f);

    #pragma unroll 2
    for (int kk = 0; kk < 64; kk += 4) {
        const float4 q0 = stW[kk];
        const float4 q1 = stW[kk + 1];
        const float4 q2 = stW[kk + 2];
        const float4 q3 = stW[kk + 3];
        if (active) {
            const float4 ea = *(const float4*)(web + __float_as_int(q0.x) + eoff);
            const float4 eb = *(const float4*)(web + __float_as_int(q0.z) + eoff);
            const float4 ec = *(const float4*)(web + __float_as_int(q1.x) + eoff);
            const float4 ed = *(const float4*)(web + __float_as_int(q1.z) + eoff);
            const float4 ee = *(const float4*)(web + __float_as_int(q2.x) + eoff);
            const float4 ef = *(const float4*)(web + __float_as_int(q2.z) + eoff);
            const float4 eg = *(const float4*)(web + __float_as_int(q3.x) + eoff);
            const float4 eh = *(const float4*)(web + __float_as_int(q3.z) + eoff);
            acc0.x += q0.y * ea.x; acc0.y += q0.y * ea.y; acc0.z += q0.y * ea.z; acc0.w += q0.y * ea.w;
            acc1.x += q0.w * eb.x; acc1.y += q0.w * eb.y; acc1.z += q0.w * eb.z; acc1.w += q0.w * eb.w;
            acc0.x += q1.y * ec.x; acc0.y += q1.y * ec.y; acc0.z += q1.y * ec.z; acc0.w += q1.y * ec.w;
            acc1.x += q1.w * ed.x; acc1.y += q1.w * ed.y; acc1.z += q1.w * ed.z; acc1.w += q1.w * ed.w;
            acc0.x += q2.y * ee.x; acc0.y += q2.y * ee.y; acc0.z += q2.y * ee.z; acc0.w += q2.y * ee.w;
            acc1.x += q2.w * ef.x; acc1.y += q2.w * ef.y; acc1.z += q2.w * ef.z; acc1.w += q2.w * ef.w;
            acc0.x += q3.y * eg.x; acc0.y += q3.y * eg.y; acc0.z += q3.y * eg.z; acc0.w += q3.y * eg.w;
            acc1.x += q3.w * eh.x; acc1.y += q3.w * eh.y; acc1.z += q3.w * eh.z; acc1.w += q3.w * eh.w;
        }
    }

    cluster.sync();   // S2: all atomics from BOTH CTAs + zpeer visible

    const float ztot = (rank == 0) ? (z_own + zpeer[0]) : (zpeer[0] + z_own);
    const float invZ = 1.0f / ztot;

    // ---- duplicate correction: counts may live in peer's bins (plain loads)
    unsigned n0, n1, n2, n3;
    {
        const int w0 = t4.x >> 2, w1 = t4.y >> 2, w2 = t4.z >> 2, w3 = t4.w >> 2;
        const unsigned int* p0 = (((unsigned)w0 & 1u) == rank ? hist : peerHist) + (w0 >> 1);
        const unsigned int* p1 = (((unsigned)w1 & 1u) == rank ? hist : peerHist) + (w1 >> 1);
        const unsigned int* p2 = (((unsigned)w2 & 1u) == rank ? hist : peerHist) + (w2 >> 1);
        const unsigned int* p3 = (((unsigned)w3 & 1u) == rank ? hist : peerHist) + (w3 >> 1);
        n0 = (*p0 >> ((t4.x & 3) << 3)) & 0xFFu;
        n1 = (*p1 >> ((t4.y & 3) << 3)) & 0xFFu;
        n2 = (*p2 >> ((t4.z & 3) << 3)) & 0xFFu;
        n3 = (*p3 >> ((t4.w & 3) << 3)) & 0xFFu;
    }
    __syncwarp();                                   // strip reuse safe

    float2* q2 = (float2*)(stage + (warp << 8));    // capacity 128 entries
    int qlen = 0;
    {
        const unsigned lt = (1u << lane) - 1u;
        unsigned m;
        m = __ballot_sync(FULLMASK, n0 > 1);
        if (n0 > 1) q2[qlen + __popc(m & lt)] =
            make_float2(__int_as_float(t4.x * (EMB * 4)), (float)(n0 - 1) * i0);
        qlen += __popc(m);
        m = __ballot_sync(FULLMASK, n1 > 1);
        if (n1 > 1) q2[qlen + __popc(m & lt)] =
            make_float2(__int_as_float(t4.y * (EMB * 4)), (float)(n1 - 1) * i1);
        qlen += __popc(m);
        m = __ballot_sync(FULLMASK, n2 > 1);
        if (n2 > 1) q2[qlen + __popc(m & lt)] =
            make_float2(__int_as_float(t4.z * (EMB * 4)), (float)(n2 - 1) * i2);
        qlen += __popc(m);
        m = __ballot_sync(FULLMASK, n3 > 1);
        if (n3 > 1) q2[qlen + __popc(m & lt)] =
            make_float2(__int_as_float(t4.w * (EMB * 4)), (float)(n3 - 1) * i3);
        qlen += __popc(m);
    }
    __syncwarp();

    for (int j = 0; j < qlen; j++) {
        const float2 e = q2[j];
        if (active) {
            const float4 ev = *(const float4*)(web + __float_as_int(e.x) + eoff);
            acc0.x += e.y * ev.x; acc0.y += e.y * ev.y;
            acc0.z += e.y * ev.z; acc0.w += e.y * ev.w;
        }
    }

    // ---- fused fc1: warp-level dot products (doc never materialized)
    acc0.x += acc1.x; acc0.y += acc1.y; acc0.z += acc1.z; acc0.w += acc1.w;
    #pragma unroll
    for (int j = 0; j < BOT; j++) {
        float s = 0.f;
        if (active) {
            const float4 w1 = *(const float4*)(fc1w + j * EMB + (lane << 2));
            s = acc0.x * w1.x + acc0.y * w1.y + acc0.z * w1.z + acc0.w * w1.w;
        }
        #pragma unroll
        for (int o = 16; o; o >>= 1) s += __shfl_xor_sync(FULLMASK, s, o);
        if (lane == 0) hw[warp * 6 + j] = s;
    }
    __syncthreads();

    // 5 threads: fixed-order 8-way sum; deposit to rank0 (pre-invZ, pre-bias)
    if (tid < BOT) {
        float h = 0.f;
        #pragma unroll
        for (int w = 0; w < 8; w++) h += hw[w * 6 + tid];
        if (rank == 0) hself[tid] = h;
        else {
            float* ph = cluster.map_shared_rank(hpeer, 0);
            ph[tid] = h;
        }
    }
    cluster.sync();   // S3: hpeer deposited

    if (rank == 0) {
        if (tid < BOT)
            hv[tid] = (hself[tid] + hpeer[tid]) * invZ + __ldg(&fc1b[tid]);
        __syncthreads();
        if (tid < EMB) {
            float o = __ldg(&fc2b[tid]);
            #pragma unroll
            for (int j = 0; j < BOT; j++) o += hv[j] * __ldg(&fc2w[tid * BOT + j]);
            out[(long long)b * EMB + tid] = o;
        }
    }
}

extern "C" void kernel_launch(void* const* d_in, const int* in_sizes, int n_in,
                              void* d_out, int out_size)
{
    const int*   x    = (const int*)  d_in[0];   // [B,S] int32 token ids
    const float* we   = (const float*)d_in[1];   // [V,EMB]
    const float* idf  = (const float*)d_in[2];   // [V]
    const float* fc1w = (const float*)d_in[3];   // [BOT,EMB]
    const float* fc1b = (const float*)d_in[4];   // [BOT]
    const float* fc2w = (const float*)d_in[5];   // [EMB,BOT]
    const float* fc2b = (const float*)d_in[6];   // [EMB]
    float* out = (float*)d_out;                  // [B,EMB]

    const int V = in_sizes[2];
    const int B = out_size / EMB;
    const int S = in_sizes[0] / B;

    const int histW = (V + 3) >> 2;
    const int histL = ((((histW + 1) >> 1) + 3) & ~3);
    size_t smem_bytes = (size_t)histL * 4
                      + (size_t)(8 * 256 + 8 + 48 + 8 + 8 + 4 + 8) * 4;

    cudaFuncSetAttribute(doc_model_kernel,
                         cudaFuncAttributeMaxDynamicSharedMemorySize,
                         (int)smem_bytes);

    doc_model_kernel<<<2 * B, NT, smem_bytes>>>(x, we, idf,
                                                fc1w, fc1b, fc2w, fc2b,
                                                out, S, V);
}

// round 14
// speedup vs baseline: 1.0169x; 1.0169x over previous
#include <cuda_runtime.h>

#define EMB 100
#define BOT 5
#define NT  512
#define B_  128
#define S_  2048
#define V_  50257
#define HW_ (((V_ + 3) / 4 + 3) & ~3)    // u32 words per row, 4 u8 counts each
#define FULLMASK 0xffffffffu

// Persistent global histogram: zero-initialized at load; every launch leaves
// it all-zero again (each CTA clears exactly the words it touched, after all
// reads). Same row -> same bins every replay, so the invariant is stable and
// the kernel is deterministic.
__device__ unsigned int g_hist[B_][HW_];

// One CTA per document row, 512 threads.
// doc = invZ * [ sum_s idf_s*emb_s + sum_{dups} (count_s-1)*idf_s*emb_s ]
// Histogram increments are L2 REDG (fire-and-forget, no SM-side pipe cost);
// the count-free main gather starts after only a __syncwarp.
__global__ void __launch_bounds__(NT, 1)
doc_model_kernel(const int* __restrict__ x,
                 const float* __restrict__ we,
                 const float* __restrict__ idf,
                 const float* __restrict__ fc1w,
                 const float* __restrict__ fc1b,
                 const float* __restrict__ fc2w,
                 const float* __restrict__ fc2b,
                 float* __restrict__ out,
                 int S, int V)
{
    __shared__ float stage[16 * 256];   // per-warp (offset,idf) pairs / dup queue
    __shared__ float zp[16];
    __shared__ float hw[16 * 6];        // fc1 warp partials
    __shared__ float hv[8];

    const int tid  = threadIdx.x;
    const int warp = tid >> 5;
    const int lane = tid & 31;
    const int b    = blockIdx.x;

    unsigned int* hrow = g_hist[b];

    // ---- token load (one LDG.128): warp w owns tokens [128w, 128w+128),
    // lane l holds tokens 128w + 4l + {0..3}.
    const int* xr = x + (long long)b * S;
    const int4 t4 = *(const int4*)(xr + (warp << 7) + (lane << 2));

    // word indices in this row's histogram
    const int w0 = t4.x >> 2, w1 = t4.y >> 2, w2 = t4.z >> 2, w3 = t4.w >> 2;

    // ---- L2 histogram increments: fire-and-forget (visible after fence+bar)
    atomicAdd(&hrow[w0], 1u << ((t4.x & 3) << 3));
    atomicAdd(&hrow[w1], 1u << ((t4.y & 3) << 3));
    atomicAdd(&hrow[w2], 1u << ((t4.z & 3) << 3));
    atomicAdd(&hrow[w3], 1u << ((t4.w & 3) << 3));

    // idf gathers
    const float i0 = __ldg(&idf[t4.x]);
    const float i1 = __ldg(&idf[t4.y]);
    const float i2 = __ldg(&idf[t4.z]);
    const float i3 = __ldg(&idf[t4.w]);

    // ---- stage (byte-offset, idf) pairs; strips are warp-private
    float4* stW = (float4*)(stage + (warp << 8));
    stW[(lane << 1)]     = make_float4(__int_as_float(t4.x * (EMB * 4)), i0,
                                       __int_as_float(t4.y * (EMB * 4)), i1);
    stW[(lane << 1) + 1] = make_float4(__int_as_float(t4.z * (EMB * 4)), i2,
                                       __int_as_float(t4.w * (EMB * 4)), i3);

    // Z partial (idf only)
    float z = (i0 + i1) + (i2 + i3);
    #pragma unroll
    for (int o = 16; o; o >>= 1) z += __shfl_xor_sync(FULLMASK, z, o);
    if (lane == 0) zp[warp] = z;
    __syncwarp();                        // stage strip ready (warp-local)

    // ---- MAIN GATHER (no CTA barrier before it; overlaps REDG completion)
    const bool active = lane < (EMB / 4);
    const int  eoff   = lane << 4;
    const char* web = (const char*)we;
    float4 acc0 = make_float4(0.f, 0.f, 0.f, 0.f);
    float4 acc1 = make_float4(0.f, 0.f, 0.f, 0.f);

    #pragma unroll 2
    for (int kk = 0; kk < 64; kk += 4) {
        const float4 q0 = stW[kk];
        const float4 q1 = stW[kk + 1];
        const float4 q2 = stW[kk + 2];
        const float4 q3 = stW[kk + 3];
        if (active) {
            const float4 ea = *(const float4*)(web + __float_as_int(q0.x) + eoff);
            const float4 eb = *(const float4*)(web + __float_as_int(q0.z) + eoff);
            const float4 ec = *(const float4*)(web + __float_as_int(q1.x) + eoff);
            const float4 ed = *(const float4*)(web + __float_as_int(q1.z) + eoff);
            const float4 ee = *(const float4*)(web + __float_as_int(q2.x) + eoff);
            const float4 ef = *(const float4*)(web + __float_as_int(q2.z) + eoff);
            const float4 eg = *(const float4*)(web + __float_as_int(q3.x) + eoff);
            const float4 eh = *(const float4*)(web + __float_as_int(q3.z) + eoff);
            acc0.x += q0.y * ea.x; acc0.y += q0.y * ea.y; acc0.z += q0.y * ea.z; acc0.w += q0.y * ea.w;
            acc1.x += q0.w * eb.x; acc1.y += q0.w * eb.y; acc1.z += q0.w * eb.z; acc1.w += q0.w * eb.w;
            acc0.x += q1.y * ec.x; acc0.y += q1.y * ec.y; acc0.z += q1.y * ec.z; acc0.w += q1.y * ec.w;
            acc1.x += q1.w * ed.x; acc1.y += q1.w * ed.y; acc1.z += q1.w * ed.z; acc1.w += q1.w * ed.w;
            acc0.x += q2.y * ee.x; acc0.y += q2.y * ee.y; acc0.z += q2.y * ee.z; acc0.w += q2.y * ee.w;
            acc1.x += q2.w * ef.x; acc1.y += q2.w * ef.y; acc1.z += q2.w * ef.z; acc1.w += q2.w * ef.w;
            acc0.x += q3.y * eg.x; acc0.y += q3.y * eg.y; acc0.z += q3.y * eg.z; acc0.w += q3.y * eg.w;
            acc1.x += q3.w * eh.x; acc1.y += q3.w * eh.y; acc1.z += q3.w * eh.z; acc1.w += q3.w * eh.w;
        }
    }

    __threadfence();     // publish this thread's REDGs
    __syncthreads();     // all threads fenced -> all counts globally visible

    float zz = 0.f;
    #pragma unroll
    for (int i = 0; i < 16; i++) zz += zp[i];
    const float invZ = 1.0f / zz;

    // ---- counts from L2 (bypass L1), duplicate correction queue
    const unsigned n0 = (__ldcg(&hrow[w0]) >> ((t4.x & 3) << 3)) & 0xFFu;
    const unsigned n1 = (__ldcg(&hrow[w1]) >> ((t4.y & 3) << 3)) & 0xFFu;
    const unsigned n2 = (__ldcg(&hrow[w2]) >> ((t4.z & 3) << 3)) & 0xFFu;
    const unsigned n3 = (__ldcg(&hrow[w3]) >> ((t4.w & 3) << 3)) & 0xFFu;
    __syncwarp();                                   // strip reuse safe

    float2* q2 = (float2*)(stage + (warp << 8));    // capacity 128 entries
    int qlen = 0;
    {
        const unsigned lt = (1u << lane) - 1u;
        unsigned m;
        m = __ballot_sync(FULLMASK, n0 > 1);
        if (n0 > 1) q2[qlen + __popc(m & lt)] =
            make_float2(__int_as_float(t4.x * (EMB * 4)), (float)(n0 - 1) * i0);
        qlen += __popc(m);
        m = __ballot_sync(FULLMASK, n1 > 1);
        if (n1 > 1) q2[qlen + __popc(m & lt)] =
            make_float2(__int_as_float(t4.y * (EMB * 4)), (float)(n1 - 1) * i1);
        qlen += __popc(m);
        m = __ballot_sync(FULLMASK, n2 > 1);
        if (n2 > 1) q2[qlen + __popc(m & lt)] =
            make_float2(__int_as_float(t4.z * (EMB * 4)), (float)(n2 - 1) * i2);
        qlen += __popc(m);
        m = __ballot_sync(FULLMASK, n3 > 1);
        if (n3 > 1) q2[qlen + __popc(m & lt)] =
            make_float2(__int_as_float(t4.w * (EMB * 4)), (float)(n3 - 1) * i3);
        qlen += __popc(m);
    }
    __syncwarp();

    for (int j = 0; j < qlen; j++) {
        const float2 e = q2[j];
        if (active) {
            const float4 ev = *(const float4*)(web + __float_as_int(e.x) + eoff);
            acc0.x += e.y * ev.x; acc0.y += e.y * ev.y;
            acc0.z += e.y * ev.z; acc0.w += e.y * ev.w;
        }
    }

    // ---- fused fc1: warp-level dot products (doc never materialized)
    acc0.x += acc1.x; acc0.y += acc1.y; acc0.z += acc1.z; acc0.w += acc1.w;
    #pragma unroll
    for (int j = 0; j < BOT; j++) {
        float s = 0.f;
        if (active) {
            const float4 w1v = *(const float4*)(fc1w + j * EMB + (lane << 2));
            s = acc0.x * w1v.x + acc0.y * w1v.y + acc0.z * w1v.z + acc0.w * w1v.w;
        }
        #pragma unroll
        for (int o = 16; o; o >>= 1) s += __shfl_xor_sync(FULLMASK, s, o);
        if (lane == 0) hw[warp * 6 + j] = s;
    }
    __syncthreads();     // hw ready; ALSO: every thread has read its counts

    // ---- clear exactly the words this CTA touched (restore all-zero state
    // for the next launch). Racing stores of 0 to a shared word are benign.
    hrow[w0] = 0u; hrow[w1] = 0u; hrow[w2] = 0u; hrow[w3] = 0u;

    // 5 threads: fixed-order 16-way sum, scale by invZ, add bias
    if (tid < BOT) {
        float h = 0.f;
        #pragma unroll
        for (int w = 0; w < 16; w++) h += hw[w * 6 + tid];
        hv[tid] = h * invZ + __ldg(&fc1b[tid]);
    }
    __syncthreads();

    // 100 threads: fc2
    if (tid < EMB) {
        float o = __ldg(&fc2b[tid]);
        #pragma unroll
        for (int j = 0; j < BOT; j++) o += hv[j] * __ldg(&fc2w[tid * BOT + j]);
        out[(long long)b * EMB + tid] = o;
    }
}

extern "C" void kernel_launch(void* const* d_in, const int* in_sizes, int n_in,
                              void* d_out, int out_size)
{
    const int*   x    = (const int*)  d_in[0];   // [B,S] int32 token ids
    const float* we   = (const float*)d_in[1];   // [V,EMB]
    const float* idf  = (const float*)d_in[2];   // [V]
    const float* fc1w = (const float*)d_in[3];   // [BOT,EMB]
    const float* fc1b = (const float*)d_in[4];   // [BOT]
    const float* fc2w = (const float*)d_in[5];   // [EMB,BOT]
    const float* fc2b = (const float*)d_in[6];   // [EMB]
    float* out = (float*)d_out;                  // [B,EMB]

    const int V = in_sizes[2];
    const int B = out_size / EMB;
    const int S = in_sizes[0] / B;

    doc_model_kernel<<<B, NT>>>(x, we, idf, fc1w, fc1b, fc2w, fc2b, out, S, V);
}